// round 2
// baseline (speedup 1.0000x reference)
#include <cuda_runtime.h>

#define EMBED_DIM 128
#define SPARSE_THRESHOLD 5

// One block per node, 128 threads = one thread per embedding dim.
// path_rows is sorted, so each node's edges form a contiguous range found by
// binary search. Nodes with degree > SPARSE_THRESHOLD are masked to zero in
// the reference, so we skip their gather work entirely (~85% of edges).
//
// NOTE: JAX x64 is disabled by default, so the "int64" arrays in the
// reference are actually int32 in the harness buffers.
__global__ void __launch_bounds__(EMBED_DIM)
path_agg_kernel(const float* __restrict__ embeds,
                const int* __restrict__ degrees,
                const int* __restrict__ rows,
                const int* __restrict__ cols,
                float* __restrict__ out,
                int n_edges)
{
    const int node = blockIdx.x;
    const int tid  = threadIdx.x;
    float* out_row = out + (size_t)node * EMBED_DIM;

    // Masked node: zero the output row and exit (d_out is poisoned, must write).
    if (degrees[node] > SPARSE_THRESHOLD) {
        out_row[tid] = 0.0f;
        return;
    }

    // Binary search: [start, end) = edges with rows[e] == node.
    // Uniform across the block; loads broadcast + hit cache.
    int lo = 0, hi = n_edges;
    while (lo < hi) {
        int mid = (lo + hi) >> 1;
        if (rows[mid] < node) lo = mid + 1; else hi = mid;
    }
    const int start = lo;
    hi = n_edges;
    while (lo < hi) {
        int mid = (lo + hi) >> 1;
        if (rows[mid] < node + 1) lo = mid + 1; else hi = mid;
    }
    const int end = lo;
    const int cnt = end - start;

    // Gather-accumulate. Unroll by 2 with independent accumulators so two
    // 512B row gathers are in flight per iteration (MLP for L2 latency).
    float acc0 = 0.0f, acc1 = 0.0f;
    int e = start;
    for (; e + 1 < end; e += 2) {
        int c0 = cols[e];
        int c1 = cols[e + 1];
        acc0 += embeds[(size_t)c0 * EMBED_DIM + tid];
        acc1 += embeds[(size_t)c1 * EMBED_DIM + tid];
    }
    if (e < end) {
        int c = cols[e];
        acc0 += embeds[(size_t)c * EMBED_DIM + tid];
    }

    const float inv = 1.0f / (float)(cnt > 0 ? cnt : 1);
    out_row[tid] = (acc0 + acc1) * inv;
}

extern "C" void kernel_launch(void* const* d_in, const int* in_sizes, int n_in,
                              void* d_out, int out_size)
{
    const float* embeds  = (const float*)d_in[0];  // [N_ENT, 128] f32
    const int*   degrees = (const int*)d_in[1];    // [N_ENT] i32 (JAX x64 off)
    const int*   rows    = (const int*)d_in[2];    // [E] i32 (sorted)
    const int*   cols    = (const int*)d_in[3];    // [E] i32

    const int n_ent   = in_sizes[1];
    const int n_edges = in_sizes[2];
    float* out = (float*)d_out;

    path_agg_kernel<<<n_ent, EMBED_DIM>>>(embeds, degrees, rows, cols, out, n_edges);
}

// round 3
// speedup vs baseline: 2.1055x; 2.1055x over previous
#include <cuda_runtime.h>

#define N_ENT 100000
#define EMBED_DIM 128
#define SPARSE_THRESHOLD 5

// Scratch: CSR row pointer built each launch (graph-capturable, no allocs).
__device__ int g_row_ptr[N_ENT + 1];

// Phase 1: boundary-detect on the sorted rows array.
// Thread e (0..E inclusive) fills row_ptr[node] = e for all nodes in
// (rows[e-1], rows[e]]  (with rows[-1] = -1, rows[E] = N).
// Result: row_ptr[node] = lower_bound(rows, node).
__global__ void rowptr_kernel(const int* __restrict__ rows,
                              int* __restrict__ row_ptr,
                              int n_edges, int n_ent)
{
    int e = blockIdx.x * blockDim.x + threadIdx.x;
    if (e > n_edges) return;
    int r    = (e < n_edges) ? rows[e]     : n_ent;
    int prev = (e > 0)       ? rows[e - 1] : -1;
    for (int node = prev + 1; node <= r; node++)
        row_ptr[node] = e;
}

// Phase 2: one warp per node. 32 lanes x float4 = 512B row per gather.
// 4 independent accumulators keep 4 row-gathers (2KB) in flight per warp.
__global__ void __launch_bounds__(256)
gather_kernel(const float4* __restrict__ embeds,
              const int* __restrict__ degrees,
              const int* __restrict__ row_ptr,
              const int* __restrict__ cols,
              float4* __restrict__ out,
              int n_ent)
{
    const int node = blockIdx.x * (blockDim.x >> 5) + (threadIdx.x >> 5);
    if (node >= n_ent) return;
    const int lane = threadIdx.x & 31;
    float4* out_row = out + (size_t)node * 32;

    if (degrees[node] > SPARSE_THRESHOLD) {
        out_row[lane] = make_float4(0.f, 0.f, 0.f, 0.f);
        return;
    }

    const int start = row_ptr[node];
    const int end   = row_ptr[node + 1];
    const int cnt   = end - start;

    float4 a0 = make_float4(0.f, 0.f, 0.f, 0.f);
    float4 a1 = a0, a2 = a0, a3 = a0;

    int e = start;
    for (; e + 4 <= end; e += 4) {
        // cols loads are uniform (broadcast) and sequential -> L1-hit.
        int c0 = __ldg(cols + e);
        int c1 = __ldg(cols + e + 1);
        int c2 = __ldg(cols + e + 2);
        int c3 = __ldg(cols + e + 3);
        // 4 independent 512B row gathers in flight.
        float4 v0 = embeds[(size_t)c0 * 32 + lane];
        float4 v1 = embeds[(size_t)c1 * 32 + lane];
        float4 v2 = embeds[(size_t)c2 * 32 + lane];
        float4 v3 = embeds[(size_t)c3 * 32 + lane];
        a0.x += v0.x; a0.y += v0.y; a0.z += v0.z; a0.w += v0.w;
        a1.x += v1.x; a1.y += v1.y; a1.z += v1.z; a1.w += v1.w;
        a2.x += v2.x; a2.y += v2.y; a2.z += v2.z; a2.w += v2.w;
        a3.x += v3.x; a3.y += v3.y; a3.z += v3.z; a3.w += v3.w;
    }
    for (; e < end; e++) {
        int c = __ldg(cols + e);
        float4 v = embeds[(size_t)c * 32 + lane];
        a0.x += v.x; a0.y += v.y; a0.z += v.z; a0.w += v.w;
    }

    const float inv = 1.0f / (float)(cnt > 0 ? cnt : 1);
    float4 r;
    r.x = (a0.x + a1.x + a2.x + a3.x) * inv;
    r.y = (a0.y + a1.y + a2.y + a3.y) * inv;
    r.z = (a0.z + a1.z + a2.z + a3.z) * inv;
    r.w = (a0.w + a1.w + a2.w + a3.w) * inv;
    out_row[lane] = r;
}

extern "C" void kernel_launch(void* const* d_in, const int* in_sizes, int n_in,
                              void* d_out, int out_size)
{
    const float4* embeds  = (const float4*)d_in[0];  // [N_ENT, 128] f32
    const int*    degrees = (const int*)d_in[1];     // [N_ENT] i32
    const int*    rows    = (const int*)d_in[2];     // [E] i32 (sorted)
    const int*    cols    = (const int*)d_in[3];     // [E] i32

    const int n_ent   = in_sizes[1];
    const int n_edges = in_sizes[2];
    float4* out = (float4*)d_out;

    int* row_ptr;
    cudaGetSymbolAddress((void**)&row_ptr, g_row_ptr);

    rowptr_kernel<<<(n_edges + 256) / 256, 256>>>(rows, row_ptr, n_edges, n_ent);

    const int warps_per_block = 256 / 32;  // 8 nodes per block
    const int grid = (n_ent + warps_per_block - 1) / warps_per_block;
    gather_kernel<<<grid, 256>>>(embeds, degrees, row_ptr, cols, out, n_ent);
}

// round 4
// speedup vs baseline: 2.1401x; 1.0164x over previous
#include <cuda_runtime.h>

#define N_ENT_MAX 100000
#define SPARSE_THRESHOLD 5

// Scratch (graph-capturable, no allocs).
__device__ int g_row_ptr[N_ENT_MAX + 1];
__device__ int g_worklist[N_ENT_MAX];
__device__ int g_count;

// ---------------------------------------------------------------------------
// Prep: fused  (a) CSR row_ptr boundary-detect over sorted rows
//              (b) node classification -> worklist of active (deg<=5) nodes
//              (c) zero-fill of masked output rows (coalesced float4 stores)
// Blocks [0, edge_blocks) do (a); blocks [edge_blocks, ...) do (b)+(c).
// ---------------------------------------------------------------------------
__global__ void __launch_bounds__(256)
prep_kernel(const int* __restrict__ rows,
            const int* __restrict__ degrees,
            int* __restrict__ row_ptr,
            float4* __restrict__ out,
            int* __restrict__ worklist,
            int* __restrict__ count,
            int n_edges, int n_ent, int edge_blocks)
{
    if (blockIdx.x < edge_blocks) {
        // (a) row_ptr[node] = lower_bound(rows, node)
        int e = blockIdx.x * 256 + threadIdx.x;
        if (e > n_edges) return;
        int r    = (e < n_edges) ? rows[e]     : n_ent;
        int prev = (e > 0)       ? rows[e - 1] : -1;
        for (int node = prev + 1; node <= r; node++)
            row_ptr[node] = e;
        return;
    }

    // (b)+(c): one thread per node for classification.
    const int base = (blockIdx.x - edge_blocks) * 256;
    const int node = base + threadIdx.x;
    const int lane = threadIdx.x & 31;

    bool active = false;
    if (node < n_ent)
        active = (degrees[node] <= SPARSE_THRESHOLD);

    unsigned act_mask = __ballot_sync(0xffffffffu, active);

    // Warp-aggregated worklist push: 1 atomic per warp.
    int n_act = __popc(act_mask);
    int ofs = 0;
    if (lane == 0 && n_act)
        ofs = atomicAdd(count, n_act);
    ofs = __shfl_sync(0xffffffffu, ofs, 0);
    if (active) {
        int rank = __popc(act_mask & ((1u << lane) - 1u));
        worklist[ofs + rank] = node;
    }

    // Cooperative zero-fill of this warp's 32 nodes that are masked.
    // Loop mask is warp-uniform; each lane stores one float4 (512B/row).
    const int warp_node_base = base + (threadIdx.x & ~31);
    const float4 z = make_float4(0.f, 0.f, 0.f, 0.f);
    unsigned inact = ~act_mask;
    while (inact) {
        int j = __ffs(inact) - 1;
        inact &= inact - 1u;
        int nz = warp_node_base + j;
        if (nz < n_ent)
            out[(size_t)nz * 32 + lane] = z;
    }
}

// ---------------------------------------------------------------------------
// Gather: one warp per ACTIVE node (grid-stride over the worklist).
// 32 lanes x float4 = 512B row; unroll 8 -> 4KB of gathers in flight.
// ---------------------------------------------------------------------------
__global__ void __launch_bounds__(256)
gather_kernel(const float4* __restrict__ embeds,
              const int* __restrict__ row_ptr,
              const int* __restrict__ cols,
              const int* __restrict__ worklist,
              const int* __restrict__ count,
              float4* __restrict__ out)
{
    const int lane = threadIdx.x & 31;
    const int warp_global = (blockIdx.x * blockDim.x + threadIdx.x) >> 5;
    const int total_warps = (gridDim.x * blockDim.x) >> 5;
    const int n_active = *count;

    for (int i = warp_global; i < n_active; i += total_warps) {
        const int node  = worklist[i];
        const int start = row_ptr[node];
        const int end   = row_ptr[node + 1];
        const int cnt   = end - start;

        float4 a0 = make_float4(0.f, 0.f, 0.f, 0.f);
        float4 a1 = a0, a2 = a0, a3 = a0;

        int e = start;
        for (; e + 8 <= end; e += 8) {
            int c0 = __ldg(cols + e);
            int c1 = __ldg(cols + e + 1);
            int c2 = __ldg(cols + e + 2);
            int c3 = __ldg(cols + e + 3);
            int c4 = __ldg(cols + e + 4);
            int c5 = __ldg(cols + e + 5);
            int c6 = __ldg(cols + e + 6);
            int c7 = __ldg(cols + e + 7);
            float4 v0 = __ldg(embeds + (size_t)c0 * 32 + lane);
            float4 v1 = __ldg(embeds + (size_t)c1 * 32 + lane);
            float4 v2 = __ldg(embeds + (size_t)c2 * 32 + lane);
            float4 v3 = __ldg(embeds + (size_t)c3 * 32 + lane);
            float4 v4 = __ldg(embeds + (size_t)c4 * 32 + lane);
            float4 v5 = __ldg(embeds + (size_t)c5 * 32 + lane);
            float4 v6 = __ldg(embeds + (size_t)c6 * 32 + lane);
            float4 v7 = __ldg(embeds + (size_t)c7 * 32 + lane);
            a0.x += v0.x + v4.x; a0.y += v0.y + v4.y; a0.z += v0.z + v4.z; a0.w += v0.w + v4.w;
            a1.x += v1.x + v5.x; a1.y += v1.y + v5.y; a1.z += v1.z + v5.z; a1.w += v1.w + v5.w;
            a2.x += v2.x + v6.x; a2.y += v2.y + v6.y; a2.z += v2.z + v6.z; a2.w += v2.w + v6.w;
            a3.x += v3.x + v7.x; a3.y += v3.y + v7.y; a3.z += v3.z + v7.z; a3.w += v3.w + v7.w;
        }
        for (; e < end; e++) {
            int c = __ldg(cols + e);
            float4 v = __ldg(embeds + (size_t)c * 32 + lane);
            a0.x += v.x; a0.y += v.y; a0.z += v.z; a0.w += v.w;
        }

        const float inv = 1.0f / (float)(cnt > 0 ? cnt : 1);
        float4 r;
        r.x = (a0.x + a1.x + a2.x + a3.x) * inv;
        r.y = (a0.y + a1.y + a2.y + a3.y) * inv;
        r.z = (a0.z + a1.z + a2.z + a3.z) * inv;
        r.w = (a0.w + a1.w + a2.w + a3.w) * inv;
        out[(size_t)node * 32 + lane] = r;
    }
}

extern "C" void kernel_launch(void* const* d_in, const int* in_sizes, int n_in,
                              void* d_out, int out_size)
{
    const float4* embeds  = (const float4*)d_in[0];  // [N_ENT, 128] f32
    const int*    degrees = (const int*)d_in[1];     // [N_ENT] i32
    const int*    rows    = (const int*)d_in[2];     // [E] i32 (sorted)
    const int*    cols    = (const int*)d_in[3];     // [E] i32

    const int n_ent   = in_sizes[1];
    const int n_edges = in_sizes[2];
    float4* out = (float4*)d_out;

    int *row_ptr, *worklist, *count;
    cudaGetSymbolAddress((void**)&row_ptr,  g_row_ptr);
    cudaGetSymbolAddress((void**)&worklist, g_worklist);
    cudaGetSymbolAddress((void**)&count,    g_count);

    cudaMemsetAsync(count, 0, sizeof(int));

    const int edge_blocks = (n_edges + 1 + 255) / 256;
    const int node_blocks = (n_ent + 255) / 256;
    prep_kernel<<<edge_blocks + node_blocks, 256>>>(
        rows, degrees, row_ptr, out, worklist, count,
        n_edges, n_ent, edge_blocks);

    // ~15% of 100k nodes expected active; 2048 blocks x 8 warps = 16384 warps,
    // grid-stride covers any count.
    gather_kernel<<<2048, 256>>>(embeds, row_ptr, cols, worklist, count, out);
}

// round 5
// speedup vs baseline: 2.4211x; 1.1313x over previous
#include <cuda_runtime.h>

#define N_ENT_MAX 100000
#define SPARSE_THRESHOLD 5

// Scratch (graph-capturable, no allocs).
__device__ int g_row_ptr[N_ENT_MAX + 1];
__device__ int g_worklist[N_ENT_MAX];
__device__ int g_count;

__device__ __forceinline__ void store_cs(float4* p, float4 v) {
    asm volatile("st.global.cs.v4.f32 [%0], {%1,%2,%3,%4};"
                 :: "l"(p), "f"(v.x), "f"(v.y), "f"(v.z), "f"(v.w) : "memory");
}

// ---------------------------------------------------------------------------
// Prep (slim): only what the gather kernel depends on.
//  (a) CSR row_ptr boundary-detect over the sorted rows array
//  (b) worklist of active (deg<=5) nodes via warp-aggregated atomics
// ---------------------------------------------------------------------------
__global__ void __launch_bounds__(256)
prep_kernel(const int* __restrict__ rows,
            const int* __restrict__ degrees,
            int* __restrict__ row_ptr,
            int* __restrict__ worklist,
            int* __restrict__ count,
            int n_edges, int n_ent, int edge_blocks)
{
    if (blockIdx.x < edge_blocks) {
        int e = blockIdx.x * 256 + threadIdx.x;
        if (e > n_edges) return;
        int r    = (e < n_edges) ? rows[e]     : n_ent;
        int prev = (e > 0)       ? rows[e - 1] : -1;
        for (int node = prev + 1; node <= r; node++)
            row_ptr[node] = e;
        return;
    }

    const int node = (blockIdx.x - edge_blocks) * 256 + threadIdx.x;
    const int lane = threadIdx.x & 31;
    bool active = (node < n_ent) && (degrees[node] <= SPARSE_THRESHOLD);

    unsigned act_mask = __ballot_sync(0xffffffffu, active);
    int n_act = __popc(act_mask);
    int ofs = 0;
    if (lane == 0 && n_act)
        ofs = atomicAdd(count, n_act);
    ofs = __shfl_sync(0xffffffffu, ofs, 0);
    if (active) {
        int rank = __popc(act_mask & ((1u << lane) - 1u));
        worklist[ofs + rank] = node;
    }
}

// ---------------------------------------------------------------------------
// Gather:
//  Phase 0: every warp zero-fills its grid-stride share of MASKED rows
//           (fire-and-forget STG.128; overlaps with phase-1 latency).
//  Phase 1: one warp per ACTIVE node from the worklist; 32 lanes x float4 =
//           512B row gathers, unroll 8 -> 4KB in flight per warp.
// ---------------------------------------------------------------------------
__global__ void __launch_bounds__(256)
gather_kernel(const float4* __restrict__ embeds,
              const int* __restrict__ degrees,
              const int* __restrict__ row_ptr,
              const int* __restrict__ cols,
              const int* __restrict__ worklist,
              const int* __restrict__ count,
              float4* __restrict__ out,
              int n_ent)
{
    const int lane = threadIdx.x & 31;
    const int warp_global = (blockIdx.x * blockDim.x + threadIdx.x) >> 5;
    const int total_warps = (gridDim.x * blockDim.x) >> 5;

    // ---- Phase 0: zero masked rows (32 nodes per warp step) ----
    const float4 z = make_float4(0.f, 0.f, 0.f, 0.f);
    for (int base = warp_global * 32; base < n_ent; base += total_warps * 32) {
        int node = base + lane;
        bool masked = (node < n_ent) && (degrees[node] > SPARSE_THRESHOLD);
        unsigned m = __ballot_sync(0xffffffffu, masked);
        while (m) {
            int j = __ffs(m) - 1;
            m &= m - 1u;
            store_cs(out + (size_t)(base + j) * 32 + lane, z);
        }
    }

    // ---- Phase 1: gather for active nodes ----
    const int n_active = *count;
    for (int i = warp_global; i < n_active; i += total_warps) {
        const int node  = worklist[i];
        const int start = row_ptr[node];
        const int end   = row_ptr[node + 1];
        const int cnt   = end - start;

        float4 a0 = make_float4(0.f, 0.f, 0.f, 0.f);
        float4 a1 = a0, a2 = a0, a3 = a0;

        int e = start;
        for (; e + 8 <= end; e += 8) {
            int c0 = __ldg(cols + e);
            int c1 = __ldg(cols + e + 1);
            int c2 = __ldg(cols + e + 2);
            int c3 = __ldg(cols + e + 3);
            int c4 = __ldg(cols + e + 4);
            int c5 = __ldg(cols + e + 5);
            int c6 = __ldg(cols + e + 6);
            int c7 = __ldg(cols + e + 7);
            float4 v0 = __ldg(embeds + (size_t)c0 * 32 + lane);
            float4 v1 = __ldg(embeds + (size_t)c1 * 32 + lane);
            float4 v2 = __ldg(embeds + (size_t)c2 * 32 + lane);
            float4 v3 = __ldg(embeds + (size_t)c3 * 32 + lane);
            float4 v4 = __ldg(embeds + (size_t)c4 * 32 + lane);
            float4 v5 = __ldg(embeds + (size_t)c5 * 32 + lane);
            float4 v6 = __ldg(embeds + (size_t)c6 * 32 + lane);
            float4 v7 = __ldg(embeds + (size_t)c7 * 32 + lane);
            a0.x += v0.x + v4.x; a0.y += v0.y + v4.y; a0.z += v0.z + v4.z; a0.w += v0.w + v4.w;
            a1.x += v1.x + v5.x; a1.y += v1.y + v5.y; a1.z += v1.z + v5.z; a1.w += v1.w + v5.w;
            a2.x += v2.x + v6.x; a2.y += v2.y + v6.y; a2.z += v2.z + v6.z; a2.w += v2.w + v6.w;
            a3.x += v3.x + v7.x; a3.y += v3.y + v7.y; a3.z += v3.z + v7.z; a3.w += v3.w + v7.w;
        }
        for (; e < end; e++) {
            int c = __ldg(cols + e);
            float4 v = __ldg(embeds + (size_t)c * 32 + lane);
            a0.x += v.x; a0.y += v.y; a0.z += v.z; a0.w += v.w;
        }

        const float inv = 1.0f / (float)(cnt > 0 ? cnt : 1);
        float4 r;
        r.x = (a0.x + a1.x + a2.x + a3.x) * inv;
        r.y = (a0.y + a1.y + a2.y + a3.y) * inv;
        r.z = (a0.z + a1.z + a2.z + a3.z) * inv;
        r.w = (a0.w + a1.w + a2.w + a3.w) * inv;
        store_cs(out + (size_t)node * 32 + lane, r);
    }
}

extern "C" void kernel_launch(void* const* d_in, const int* in_sizes, int n_in,
                              void* d_out, int out_size)
{
    const float4* embeds  = (const float4*)d_in[0];  // [N_ENT, 128] f32
    const int*    degrees = (const int*)d_in[1];     // [N_ENT] i32
    const int*    rows    = (const int*)d_in[2];     // [E] i32 (sorted)
    const int*    cols    = (const int*)d_in[3];     // [E] i32

    const int n_ent   = in_sizes[1];
    const int n_edges = in_sizes[2];
    float4* out = (float4*)d_out;

    int *row_ptr, *worklist, *count;
    cudaGetSymbolAddress((void**)&row_ptr,  g_row_ptr);
    cudaGetSymbolAddress((void**)&worklist, g_worklist);
    cudaGetSymbolAddress((void**)&count,    g_count);

    cudaMemsetAsync(count, 0, sizeof(int));

    const int edge_blocks = (n_edges + 1 + 255) / 256;
    const int node_blocks = (n_ent + 255) / 256;
    prep_kernel<<<edge_blocks + node_blocks, 256>>>(
        rows, degrees, row_ptr, worklist, count, n_edges, n_ent, edge_blocks);

    gather_kernel<<<2048, 256>>>(embeds, degrees, row_ptr, cols,
                                 worklist, count, out, n_ent);
}

// round 6
// speedup vs baseline: 2.8703x; 1.1855x over previous
#include <cuda_runtime.h>

#define N_ENT_MAX 100000
#define SPARSE_THRESHOLD 5

// Scratch (graph-capturable, no allocs).
__device__ int g_row_ptr[N_ENT_MAX + 1];
__device__ int g_worklist[N_ENT_MAX];
__device__ int g_count;

__device__ __forceinline__ void store_cs(float4* p, float4 v) {
    asm volatile("st.global.cs.v4.f32 [%0], {%1,%2,%3,%4};"
                 :: "l"(p), "f"(v.x), "f"(v.y), "f"(v.z), "f"(v.w) : "memory");
}

// ---------------------------------------------------------------------------
// Prep: (a) CSR row_ptr boundary-detect, 4 edges/thread via int4
//       (b) worklist of active (deg<=5) nodes, warp-aggregated atomics
// ---------------------------------------------------------------------------
__global__ void __launch_bounds__(256)
prep_kernel(const int* __restrict__ rows,
            const int* __restrict__ degrees,
            int* __restrict__ row_ptr,
            int* __restrict__ worklist,
            int* __restrict__ count,
            int n_edges, int n_ent, int edge_blocks)
{
    if (blockIdx.x < edge_blocks) {
        // Each thread owns edges [4t, 4t+4); writes row_ptr for boundaries.
        int t  = blockIdx.x * 256 + threadIdx.x;
        int e0 = t * 4;
        if (e0 > n_edges) return;

        int r[5];
        r[0] = (e0 > 0) ? rows[e0 - 1] : -1;
        if (e0 + 4 <= n_edges) {
            int4 v = *(const int4*)(rows + e0);   // rows 16B-aligned at 4*e0
            r[1] = v.x; r[2] = v.y; r[3] = v.z; r[4] = v.w;
        } else {
            #pragma unroll
            for (int k = 0; k < 4; k++)
                r[k + 1] = (e0 + k < n_edges) ? rows[e0 + k] : n_ent;
        }
        #pragma unroll
        for (int k = 0; k < 4; k++) {
            int e = e0 + k;
            if (e > n_edges) break;
            for (int node = r[k] + 1; node <= r[k + 1]; node++)
                row_ptr[node] = e;
        }
        return;
    }

    const int node = (blockIdx.x - edge_blocks) * 256 + threadIdx.x;
    const int lane = threadIdx.x & 31;
    bool active = (node < n_ent) && (degrees[node] <= SPARSE_THRESHOLD);

    unsigned act_mask = __ballot_sync(0xffffffffu, active);
    int n_act = __popc(act_mask);
    int ofs = 0;
    if (lane == 0 && n_act)
        ofs = atomicAdd(count, n_act);
    ofs = __shfl_sync(0xffffffffu, ofs, 0);
    if (active) {
        int rank = __popc(act_mask & ((1u << lane) - 1u));
        worklist[ofs + rank] = node;
    }
}

// ---------------------------------------------------------------------------
// Gather (persistent, one wave = 148*6 blocks):
//  Phase 0: zero-fill masked rows (grid-stride, 32 nodes/warp/step).
//  Phase 1: one warp per active node from the worklist; 512B row gathers,
//           unroll 8 (4KB in flight), 2 accumulators (reg diet for occ).
// ---------------------------------------------------------------------------
__global__ void __launch_bounds__(256, 6)
gather_kernel(const float4* __restrict__ embeds,
              const int* __restrict__ degrees,
              const int* __restrict__ row_ptr,
              const int* __restrict__ cols,
              const int* __restrict__ worklist,
              const int* __restrict__ count,
              float4* __restrict__ out,
              int n_ent)
{
    const int lane = threadIdx.x & 31;
    const int warp_global = (blockIdx.x * blockDim.x + threadIdx.x) >> 5;
    const int total_warps = (gridDim.x * blockDim.x) >> 5;

    // ---- Phase 0: zero masked rows ----
    const float4 z = make_float4(0.f, 0.f, 0.f, 0.f);
    for (int base = warp_global * 32; base < n_ent; base += total_warps * 32) {
        int node = base + lane;
        bool masked = (node < n_ent) && (degrees[node] > SPARSE_THRESHOLD);
        unsigned m = __ballot_sync(0xffffffffu, masked);
        while (m) {
            int j = __ffs(m) - 1;
            m &= m - 1u;
            store_cs(out + (size_t)(base + j) * 32 + lane, z);
        }
    }

    // ---- Phase 1: gather for active nodes ----
    const int n_active = *count;
    for (int i = warp_global; i < n_active; i += total_warps) {
        const int node  = worklist[i];
        const int start = row_ptr[node];
        const int end   = row_ptr[node + 1];
        const int cnt   = end - start;

        float4 a0 = make_float4(0.f, 0.f, 0.f, 0.f);
        float4 a1 = a0;

        int e = start;
        for (; e + 8 <= end; e += 8) {
            int c0 = __ldg(cols + e);
            int c1 = __ldg(cols + e + 1);
            int c2 = __ldg(cols + e + 2);
            int c3 = __ldg(cols + e + 3);
            int c4 = __ldg(cols + e + 4);
            int c5 = __ldg(cols + e + 5);
            int c6 = __ldg(cols + e + 6);
            int c7 = __ldg(cols + e + 7);
            float4 v0 = __ldg(embeds + (size_t)c0 * 32 + lane);
            float4 v1 = __ldg(embeds + (size_t)c1 * 32 + lane);
            float4 v2 = __ldg(embeds + (size_t)c2 * 32 + lane);
            float4 v3 = __ldg(embeds + (size_t)c3 * 32 + lane);
            float4 v4 = __ldg(embeds + (size_t)c4 * 32 + lane);
            float4 v5 = __ldg(embeds + (size_t)c5 * 32 + lane);
            float4 v6 = __ldg(embeds + (size_t)c6 * 32 + lane);
            float4 v7 = __ldg(embeds + (size_t)c7 * 32 + lane);
            a0.x += (v0.x + v2.x) + (v4.x + v6.x);
            a0.y += (v0.y + v2.y) + (v4.y + v6.y);
            a0.z += (v0.z + v2.z) + (v4.z + v6.z);
            a0.w += (v0.w + v2.w) + (v4.w + v6.w);
            a1.x += (v1.x + v3.x) + (v5.x + v7.x);
            a1.y += (v1.y + v3.y) + (v5.y + v7.y);
            a1.z += (v1.z + v3.z) + (v5.z + v7.z);
            a1.w += (v1.w + v3.w) + (v5.w + v7.w);
        }
        for (; e < end; e++) {
            int c = __ldg(cols + e);
            float4 v = __ldg(embeds + (size_t)c * 32 + lane);
            a0.x += v.x; a0.y += v.y; a0.z += v.z; a0.w += v.w;
        }

        const float inv = 1.0f / (float)(cnt > 0 ? cnt : 1);
        float4 r;
        r.x = (a0.x + a1.x) * inv;
        r.y = (a0.y + a1.y) * inv;
        r.z = (a0.z + a1.z) * inv;
        r.w = (a0.w + a1.w) * inv;
        store_cs(out + (size_t)node * 32 + lane, r);
    }
}

extern "C" void kernel_launch(void* const* d_in, const int* in_sizes, int n_in,
                              void* d_out, int out_size)
{
    const float4* embeds  = (const float4*)d_in[0];  // [N_ENT, 128] f32
    const int*    degrees = (const int*)d_in[1];     // [N_ENT] i32
    const int*    rows    = (const int*)d_in[2];     // [E] i32 (sorted)
    const int*    cols    = (const int*)d_in[3];     // [E] i32

    const int n_ent   = in_sizes[1];
    const int n_edges = in_sizes[2];
    float4* out = (float4*)d_out;

    int *row_ptr, *worklist, *count;
    cudaGetSymbolAddress((void**)&row_ptr,  g_row_ptr);
    cudaGetSymbolAddress((void**)&worklist, g_worklist);
    cudaGetSymbolAddress((void**)&count,    g_count);

    cudaMemsetAsync(count, 0, sizeof(int));

    // 4 edges per thread in the rowptr section.
    const int edge_threads = n_edges / 4 + 1;
    const int edge_blocks  = (edge_threads + 255) / 256;
    const int node_blocks  = (n_ent + 255) / 256;
    prep_kernel<<<edge_blocks + node_blocks, 256>>>(
        rows, degrees, row_ptr, worklist, count, n_edges, n_ent, edge_blocks);

    // Persistent one-wave grid: 148 SMs x 6 blocks.
    gather_kernel<<<148 * 6, 256>>>(embeds, degrees, row_ptr, cols,
                                    worklist, count, out, n_ent);
}